// round 5
// baseline (speedup 1.0000x reference)
#include <cuda_runtime.h>
#include <cuda_bf16.h>
#include <stdint.h>

// ---------------------------------------------------------------------------
// MMD loss, sm_103-portable tensor path (mma.sync bf16 + ldmatrix + cp.async).
// Z = [X; Y] (16384 x 256, fp32 -> bf16). G = Z Z^T over the lower triangle in
// 128x128 CTA tiles. Fused epilogue: exp(-(x2+y2-2d)/sigma) with pair factor
// f in {0,1,2} (strictly-lower=2, diag=1, upper=0) and region sign (+1 XX/YY,
// -1 cross), reconstructing sumXX + sumYY - 2 sumXY exactly. Per-tile double
// partials reduced deterministically by a final kernel.
// ---------------------------------------------------------------------------

#define NROWS_  8192
#define DIM_    256
#define NZ_     16384
#define BT_     128                       // CTA tile (M == N)
#define NBI_    (NZ_ / BT_)               // 128
#define NTILES_ (NBI_ * (NBI_ + 1) / 2)   // 8256
#define TPB_    256

// exp(-sq/sigma) = 2^(sq * CEXP_), sigma = 256
#define CEXP_ (-1.4426950408889634f / 256.0f)

// ------------------------------ device scratch -----------------------------
__device__ __align__(16) __nv_bfloat16 g_Zb[(size_t)NZ_ * DIM_]; // 8 MB
__device__ float  g_z2[NZ_];
__device__ double g_part[NTILES_];

// ------------------------------ PTX helpers --------------------------------
__device__ __forceinline__ uint32_t smem_u32(const void* p) {
    uint32_t a;
    asm("{ .reg .u64 t; cvta.to.shared.u64 t, %1; cvt.u32.u64 %0, t; }"
        : "=r"(a) : "l"(p));
    return a;
}

#define CP_ASYNC16(saddr, gptr) \
    asm volatile("cp.async.cg.shared.global [%0], [%1], 16;" \
                 :: "r"(saddr), "l"(gptr) : "memory")
#define CP_COMMIT() asm volatile("cp.async.commit_group;" ::: "memory")
#define CP_WAIT(n)  asm volatile("cp.async.wait_group %0;" :: "n"(n) : "memory")

#define LDSM4(r0, r1, r2, r3, addr) \
    asm volatile("ldmatrix.sync.aligned.m8n8.x4.shared.b16 {%0,%1,%2,%3}, [%4];" \
                 : "=r"(r0), "=r"(r1), "=r"(r2), "=r"(r3) : "r"(addr))

#define MMA16816(c, a, b) \
    asm volatile( \
        "mma.sync.aligned.m16n8k16.row.col.f32.bf16.bf16.f32 " \
        "{%0,%1,%2,%3}, {%4,%5,%6,%7}, {%8,%9}, {%0,%1,%2,%3};" \
        : "+f"((c)[0]), "+f"((c)[1]), "+f"((c)[2]), "+f"((c)[3]) \
        : "r"((a)[0]), "r"((a)[1]), "r"((a)[2]), "r"((a)[3]), \
          "r"((b)[0]), "r"((b)[1]))

// ------------------------------ prep kernel --------------------------------
// One block per Z row: bf16-convert, fp32 |z|^2.
__global__ void __launch_bounds__(DIM_) mmd_prep(const float* __restrict__ X,
                                                 const float* __restrict__ Y) {
    int row = blockIdx.x;
    int col = threadIdx.x;
    const float* src = (row < NROWS_) ? (X + (size_t)row * DIM_)
                                      : (Y + (size_t)(row - NROWS_) * DIM_);
    float v = src[col];
    g_Zb[(size_t)row * DIM_ + col] = __float2bfloat16(v);
    float s = v * v;
#pragma unroll
    for (int o = 16; o; o >>= 1) s += __shfl_xor_sync(0xffffffffu, s, o);
    __shared__ float ws[8];
    if ((col & 31) == 0) ws[col >> 5] = s;
    __syncthreads();
    if (col == 0) {
        float t = 0.f;
#pragma unroll
        for (int i = 0; i < 8; i++) t += ws[i];
        g_z2[row] = t;
    }
}

// ------------------------------ main kernel --------------------------------
// Dynamic SMEM layout:
//   [0..512)     x2 tile  (128 fp32, rows RI..)
//   [512..1024)  y2 tile  (128 fp32, cols RJ..)
//   [1024..)     2 stages x (A 16KB + B 16KB), swizzled bf16, 1024-aligned
#define SOFF_X2   0
#define SOFF_Y2   512
#define SOFF_TILE 1024
#define ASZ_   (BT_ * 128)            // 16384 bytes (128 rows x 64 bf16)
#define STAGE_ (2 * ASZ_)             // 32768
#define SMEM_DYN_ (SOFF_TILE + 2 * STAGE_)   // 66560

__global__ void __launch_bounds__(TPB_, 2) mmd_main() {
    extern __shared__ char smem[];
    const uint32_t sb = smem_u32(smem);
    const int tid  = threadIdx.x;
    const int wid  = tid >> 5;
    const int lane = tid & 31;
    const int wm   = wid >> 2;        // 0..1  (M warp row, 64 rows each)
    const int wn   = wid & 3;         // 0..3  (N warp col, 32 cols each)

    // --- triangular tile decode: t -> (bi, bj), bj <= bi ---
    const int t = blockIdx.x;
    int bi = (int)floorf((sqrtf(8.0f * (float)t + 1.0f) - 1.0f) * 0.5f);
    while ((bi + 1) * (bi + 2) / 2 <= t) bi++;
    while (bi * (bi + 1) / 2 > t) bi--;
    const int bj = t - bi * (bi + 1) / 2;
    const int RI = bi * BT_;
    const int RJ = bj * BT_;

    // --- stage x2 / y2 ---
    if (tid < 128)
        *reinterpret_cast<float*>(smem + SOFF_X2 + tid * 4) = g_z2[RI + tid];
    else
        *reinterpret_cast<float*>(smem + SOFF_Y2 + (tid - 128) * 4) =
            g_z2[RJ + tid - 128];

    // --- cp.async tile loader: chunk c -> buffer (c&1) ---
    // A: rows RI.., B: rows RJ..; each 128 rows x 64 bf16, SW128 swizzle.
    const int r8  = tid >> 3;         // 0..31   (row group base, step 32 rows)
    const int seg = tid & 7;          // 16B segment within 128B row
    auto load_chunk = [&](int c) {
        const int kb = c * 64;
        const uint32_t base = sb + SOFF_TILE + (c & 1) * STAGE_;
#pragma unroll
        for (int i = 0; i < 4; ++i) {
            int r = i * 32 + r8;
            uint32_t off = (uint32_t)(r * 128 + seg * 16);
            off ^= (off >> 3) & 0x70;
            CP_ASYNC16(base + off,
                       &g_Zb[(size_t)(RI + r) * DIM_ + kb + seg * 8]);
        }
#pragma unroll
        for (int i = 0; i < 4; ++i) {
            int r = i * 32 + r8;
            uint32_t off = (uint32_t)(r * 128 + seg * 16);
            off ^= (off >> 3) & 0x70;
            CP_ASYNC16(base + ASZ_ + off,
                       &g_Zb[(size_t)(RJ + r) * DIM_ + kb + seg * 8]);
        }
        CP_COMMIT();
    };

    float acc[4][4][4];
#pragma unroll
    for (int mt = 0; mt < 4; ++mt)
#pragma unroll
        for (int nt = 0; nt < 4; ++nt)
#pragma unroll
            for (int e = 0; e < 4; ++e) acc[mt][nt][e] = 0.f;

    // Pre-computed ldmatrix lane addresses (row, kbyte-add within 32B step)
    const int a_row = wm * 64 + (lane & 15);          // + mt*16
    const int a_kad = (lane & 16) ? 16 : 0;
    const int b_row = wn * 32 + (lane & 7) + ((lane & 16) ? 8 : 0); // + nh*16
    const int b_kad = (lane & 8) ? 16 : 0;

    load_chunk(0);
#pragma unroll 1
    for (int c = 0; c < 4; ++c) {
        if (c < 3) load_chunk(c + 1);
        if (c < 3) { CP_WAIT(1); } else { CP_WAIT(0); }
        __syncthreads();
        const uint32_t sA = sb + SOFF_TILE + (c & 1) * STAGE_;
        const uint32_t sB = sA + ASZ_;
#pragma unroll
        for (int ks = 0; ks < 4; ++ks) {
            uint32_t a[4][4], b[2][4];
#pragma unroll
            for (int mt = 0; mt < 4; ++mt) {
                uint32_t off =
                    (uint32_t)((a_row + mt * 16) * 128 + ks * 32 + a_kad);
                off ^= (off >> 3) & 0x70;
                LDSM4(a[mt][0], a[mt][1], a[mt][2], a[mt][3], sA + off);
            }
#pragma unroll
            for (int nh = 0; nh < 2; ++nh) {
                uint32_t off =
                    (uint32_t)((b_row + nh * 16) * 128 + ks * 32 + b_kad);
                off ^= (off >> 3) & 0x70;
                LDSM4(b[nh][0], b[nh][1], b[nh][2], b[nh][3], sB + off);
            }
#pragma unroll
            for (int mt = 0; mt < 4; ++mt) {
#pragma unroll
                for (int nt = 0; nt < 4; ++nt) {
                    // b-frag for nt: half nh = nt>>1, regs {0,1} or {2,3}
                    uint32_t bf[2] = { b[nt >> 1][(nt & 1) * 2],
                                       b[nt >> 1][(nt & 1) * 2 + 1] };
                    MMA16816(acc[mt][nt], a[mt], bf);
                }
            }
        }
        __syncthreads();
    }

    // --- fused epilogue straight from accumulator registers ---
    const float* x2s = reinterpret_cast<const float*>(smem + SOFF_X2);
    const float* y2s = reinterpret_cast<const float*>(smem + SOFF_Y2);
    const int grp = lane >> 2;
    const int tig = lane & 3;
    float lsum = 0.f;
#pragma unroll
    for (int mt = 0; mt < 4; ++mt) {
        const int r0 = wm * 64 + mt * 16 + grp;      // local row of c0/c1
#pragma unroll
        for (int nt = 0; nt < 4; ++nt) {
            const int c0 = wn * 32 + nt * 8 + tig * 2;   // local col
#pragma unroll
            for (int e = 0; e < 4; ++e) {
                const int rl = r0 + ((e >> 1) ? 8 : 0);
                const int cl = c0 + (e & 1);
                const int rg = RI + rl, cg = RJ + cl;
                float sq = x2s[rl] + y2s[cl] - 2.0f * acc[mt][nt][e];
                float ex;
                asm("ex2.approx.f32 %0, %1;" : "=f"(ex) : "f"(sq * CEXP_));
                float f = (cg < rg) ? 2.0f : ((cg == rg) ? 1.0f : 0.0f);
                lsum += f * ex;
            }
        }
    }
#pragma unroll
    for (int o = 16; o; o >>= 1) lsum += __shfl_xor_sync(0xffffffffu, lsum, o);
    __shared__ float wsum[8];
    if (lane == 0) wsum[wid] = lsum;
    __syncthreads();
    if (tid == 0) {
        float tot = 0.f;
#pragma unroll
        for (int i = 0; i < 8; ++i) tot += wsum[i];
        float sgn = ((RI < NROWS_) == (RJ < NROWS_)) ? 1.0f : -1.0f;
        g_part[t] = (double)sgn * (double)tot;
    }
}

// ------------------------------ finalize -----------------------------------
__global__ void __launch_bounds__(256) mmd_final(float* __restrict__ out) {
    __shared__ double sm[256];
    double s = 0.0;
    for (int i = threadIdx.x; i < NTILES_; i += 256) s += g_part[i];
    sm[threadIdx.x] = s;
    __syncthreads();
    for (int st = 128; st > 0; st >>= 1) {
        if (threadIdx.x < st) sm[threadIdx.x] += sm[threadIdx.x + st];
        __syncthreads();
    }
    if (threadIdx.x == 0)
        out[0] = (float)(sm[0] * (1.0 / ((double)NROWS_ * (double)NROWS_)));
}

// ------------------------------ launch -------------------------------------
extern "C" void kernel_launch(void* const* d_in, const int* in_sizes, int n_in,
                              void* d_out, int out_size) {
    (void)in_sizes; (void)n_in; (void)out_size;
    const float* X = (const float*)d_in[0];
    const float* Y = (const float*)d_in[1];
    // sigma is the fixed scalar 256, folded into CEXP_.

    static bool attr_done = false;
    if (!attr_done) {
        cudaFuncSetAttribute(mmd_main,
                             cudaFuncAttributeMaxDynamicSharedMemorySize,
                             SMEM_DYN_);
        attr_done = true;
    }

    mmd_prep<<<NZ_, DIM_>>>(X, Y);
    mmd_main<<<NTILES_, TPB_, SMEM_DYN_>>>();
    mmd_final<<<1, 256>>>((float*)d_out);
}